// round 8
// baseline (speedup 1.0000x reference)
#include <cuda_runtime.h>
#include <cuda_bf16.h>
#include <cstdint>

#define T_TOK 8192
#define HDIM  2048
#define NEXP  8

// GEMM tile config (int8 IMMA path; tcgen05 not available under compute_103)
#define BM 128
#define BN 128
#define BKC 128                    // K elems per chunk = 128 int8 = 128B rows (SW128)
#define NCHUNK (HDIM / BKC)        // 16
#define NSTAGE 3
// per-stage SMEM regions (bytes): 4 x 16KB
#define A_Q1_OFF 0
#define A_Q2_OFF 16384
#define B_Q1_OFF 32768
#define B_Q2_OFF 49152
#define STAGE_BYTES 65536
#define SM_HDR 2048
#define SMEM_TOTAL (SM_HDR + NSTAGE * STAGE_BYTES)   // 198656

// ---------------- device scratch (no allocations allowed) -------------------
__device__ int    d_cnt[NEXP];
__device__ int    d_list[NEXP * T_TOK];
__device__ float  d_gatev[NEXP * T_TOK];
__device__ float  d_xscale[T_TOK];
__device__ float  d_wscale[NEXP * HDIM];          // sB per (e, n)
__device__ float  d_winv[NEXP * HDIM];            // 127/colmax
__device__ signed char d_xq1[(size_t)T_TOK * HDIM];
__device__ signed char d_xq2[(size_t)T_TOK * HDIM];
__device__ signed char d_wq1[(size_t)NEXP * HDIM * HDIM];   // We^T [e][n][k]
__device__ signed char d_wq2[(size_t)NEXP * HDIM * HDIM];

// ---------------- helpers ---------------------------------------------------
__device__ __forceinline__ uint32_t smem_u32(const void* p) {
    uint32_t a;
    asm("{ .reg .u64 t; cvta.to.shared.u64 t, %1; cvt.u32.u64 %0, t; }" : "=r"(a) : "l"(p));
    return a;
}
__device__ __forceinline__ void cp16(uint32_t dst, const void* src) {
    asm volatile("cp.async.cg.shared.global [%0], [%1], 16;" :: "r"(dst), "l"(src));
}
__device__ __forceinline__ void ldm4(uint32_t addr, uint32_t& r0, uint32_t& r1,
                                     uint32_t& r2, uint32_t& r3) {
    asm volatile("ldmatrix.sync.aligned.m8n8.x4.shared.b16 {%0,%1,%2,%3}, [%4];"
                 : "=r"(r0), "=r"(r1), "=r"(r2), "=r"(r3) : "r"(addr));
}
__device__ __forceinline__ void imma16832(int* c, const uint32_t* a,
                                          uint32_t b0, uint32_t b1) {
    asm volatile(
        "mma.sync.aligned.m16n8k32.row.col.s32.s8.s8.s32 "
        "{%0,%1,%2,%3}, {%4,%5,%6,%7}, {%8,%9}, {%0,%1,%2,%3};"
        : "+r"(c[0]), "+r"(c[1]), "+r"(c[2]), "+r"(c[3])
        : "r"(a[0]), "r"(a[1]), "r"(a[2]), "r"(a[3]), "r"(b0), "r"(b1));
}

// ---------------- kernel 0: init --------------------------------------------
__global__ void init_kernel(float* __restrict__ out) {
    int i = blockIdx.x * blockDim.x + threadIdx.x;
    if (i < NEXP) d_cnt[i] = 0;
    const int n4 = (T_TOK * HDIM) / 4;
    float4 z = make_float4(0.f, 0.f, 0.f, 0.f);
    float4* o4 = (float4*)out;
    for (int j = i; j < n4; j += gridDim.x * blockDim.x) o4[j] = z;
}

// ---------------- kernel 1: quantize x (warp per token row) ------------------
__global__ void quant_x(const float* __restrict__ x) {
    const int t = (blockIdx.x * blockDim.x + threadIdx.x) >> 5;
    if (t >= T_TOK) return;
    const int lane = threadIdx.x & 31;
    const float4* xr = (const float4*)(x + (size_t)t * HDIM);

    float amax = 0.f;
#pragma unroll
    for (int j = 0; j < 16; j++) {
        float4 v = xr[lane + 32 * j];
        amax = fmaxf(amax, fmaxf(fmaxf(fabsf(v.x), fabsf(v.y)), fmaxf(fabsf(v.z), fabsf(v.w))));
    }
#pragma unroll
    for (int s = 16; s > 0; s >>= 1)
        amax = fmaxf(amax, __shfl_xor_sync(0xFFFFFFFFu, amax, s));
    amax = fmaxf(amax, 1e-20f);
    const float sA = amax * (1.f / 127.f);
    const float inv = 127.f / amax;

    char4* q1 = (char4*)(d_xq1 + (size_t)t * HDIM);
    char4* q2 = (char4*)(d_xq2 + (size_t)t * HDIM);
#pragma unroll
    for (int j = 0; j < 16; j++) {
        float4 v = xr[lane + 32 * j];
        int a0 = __float2int_rn(v.x * inv), a1 = __float2int_rn(v.y * inv);
        int a2 = __float2int_rn(v.z * inv), a3 = __float2int_rn(v.w * inv);
        float r0 = v.x - a0 * sA, r1 = v.y - a1 * sA;
        float r2 = v.z - a2 * sA, r3 = v.w - a3 * sA;
        int c0 = __float2int_rn(r0 * inv * 128.f), c1 = __float2int_rn(r1 * inv * 128.f);
        int c2 = __float2int_rn(r2 * inv * 128.f), c3 = __float2int_rn(r3 * inv * 128.f);
        q1[lane + 32 * j] = make_char4((signed char)a0, (signed char)a1,
                                       (signed char)a2, (signed char)a3);
        q2[lane + 32 * j] = make_char4((signed char)c0, (signed char)c1,
                                       (signed char)c2, (signed char)c3);
    }
    if (lane == 0) d_xscale[t] = sA;
}

// ---------------- kernel 2a: column abs-max of We ----------------------------
__global__ void colmax_w(const float* __restrict__ We) {
    const int n = blockIdx.x * blockDim.x + threadIdx.x;
    const int e = blockIdx.y;
    const float* col = We + (size_t)e * HDIM * HDIM + n;
    float amax = 0.f;
#pragma unroll 4
    for (int k = 0; k < HDIM; k++)
        amax = fmaxf(amax, fabsf(col[(size_t)k * HDIM]));
    amax = fmaxf(amax, 1e-20f);
    d_wscale[e * HDIM + n] = amax * (1.f / 127.f);
    d_winv[e * HDIM + n]   = 127.f / amax;
}

// ---------------- kernel 2b: transpose + quantize We -------------------------
__global__ void quant_w(const float* __restrict__ We) {
    __shared__ float tile[32][33];
    int e = blockIdx.z;
    int n0 = blockIdx.x * 32, k0 = blockIdx.y * 32;
    int tx = threadIdx.x & 31, ty = threadIdx.x >> 5;   // 32 x 8
    const float* src = We + ((size_t)e * HDIM + k0) * HDIM + n0;
#pragma unroll
    for (int i = 0; i < 4; i++)
        tile[ty + 8 * i][tx] = src[(size_t)(ty + 8 * i) * HDIM + tx];
    __syncthreads();
    size_t ob = ((size_t)e * HDIM + n0) * HDIM + k0;
#pragma unroll
    for (int i = 0; i < 4; i++) {
        const int nl = ty + 8 * i;                       // local n row
        const float inv = d_winv[e * HDIM + n0 + nl];
        const float sB  = d_wscale[e * HDIM + n0 + nl];
        float v = tile[tx][nl];
        int b1 = __float2int_rn(v * inv);
        float r = v - b1 * sB;
        int b2 = __float2int_rn(r * inv * 128.f);
        d_wq1[ob + (size_t)nl * HDIM + tx] = (signed char)b1;
        d_wq2[ob + (size_t)nl * HDIM + tx] = (signed char)b2;
    }
}

// ---------------- kernel 3: router (warp per token) --------------------------
__global__ void router_kernel(const float* __restrict__ x,
                              const float* __restrict__ Wg,
                              const float* __restrict__ bg) {
    const int wid_g = (blockIdx.x * blockDim.x + threadIdx.x) >> 5;
    if (wid_g >= T_TOK) return;
    const int lane = threadIdx.x & 31;
    const int t = wid_g;

    float acc[NEXP];
#pragma unroll
    for (int e = 0; e < NEXP; e++) acc[e] = 0.f;

    const float4* xr = (const float4*)(x + (size_t)t * HDIM);
#pragma unroll 4
    for (int j = 0; j < HDIM / 4 / 32; j++) {
        const int i4 = lane + j * 32;
        float4 xv = xr[i4];
        const int h = i4 * 4;
        const float4* wr = (const float4*)(Wg + (size_t)h * NEXP);
        float4 w0 = wr[0], w1 = wr[1], w2 = wr[2], w3 = wr[3];
        float4 w4 = wr[4], w5 = wr[5], w6 = wr[6], w7 = wr[7];
        acc[0] += xv.x * w0.x; acc[1] += xv.x * w0.y; acc[2] += xv.x * w0.z; acc[3] += xv.x * w0.w;
        acc[4] += xv.x * w1.x; acc[5] += xv.x * w1.y; acc[6] += xv.x * w1.z; acc[7] += xv.x * w1.w;
        acc[0] += xv.y * w2.x; acc[1] += xv.y * w2.y; acc[2] += xv.y * w2.z; acc[3] += xv.y * w2.w;
        acc[4] += xv.y * w3.x; acc[5] += xv.y * w3.y; acc[6] += xv.y * w3.z; acc[7] += xv.y * w3.w;
        acc[0] += xv.z * w4.x; acc[1] += xv.z * w4.y; acc[2] += xv.z * w4.z; acc[3] += xv.z * w4.w;
        acc[4] += xv.z * w5.x; acc[5] += xv.z * w5.y; acc[6] += xv.z * w5.z; acc[7] += xv.z * w5.w;
        acc[0] += xv.w * w6.x; acc[1] += xv.w * w6.y; acc[2] += xv.w * w6.z; acc[3] += xv.w * w6.w;
        acc[4] += xv.w * w7.x; acc[5] += xv.w * w7.y; acc[6] += xv.w * w7.z; acc[7] += xv.w * w7.w;
    }
#pragma unroll
    for (int e = 0; e < NEXP; e++) {
#pragma unroll
        for (int s = 16; s > 0; s >>= 1)
            acc[e] += __shfl_xor_sync(0xFFFFFFFFu, acc[e], s);
    }
    if (lane == 0) {
#pragma unroll
        for (int e = 0; e < NEXP; e++) acc[e] += bg[e];
        float m = acc[0];
#pragma unroll
        for (int e = 1; e < NEXP; e++) m = fmaxf(m, acc[e]);
        float p[NEXP], s = 0.f;
#pragma unroll
        for (int e = 0; e < NEXP; e++) { p[e] = __expf(acc[e] - m); s += p[e]; }
        float inv = 1.f / s;
#pragma unroll
        for (int e = 0; e < NEXP; e++) p[e] *= inv;
        int i0 = 0;
#pragma unroll
        for (int e = 1; e < NEXP; e++) if (p[e] > p[i0]) i0 = e;
        int i1 = (i0 == 0) ? 1 : 0;
#pragma unroll
        for (int e = 0; e < NEXP; e++) if (e != i0 && p[e] > p[i1]) i1 = e;
        int pos0 = atomicAdd(&d_cnt[i0], 1);
        d_list[i0 * T_TOK + pos0] = t;  d_gatev[i0 * T_TOK + pos0] = p[i0];
        int pos1 = atomicAdd(&d_cnt[i1], 1);
        d_list[i1 * T_TOK + pos1] = t;  d_gatev[i1 * T_TOK + pos1] = p[i1];
    }
}

// ---------------- kernel 4: grouped GEMM via int8 IMMA, 2-term ---------------
__global__ void __launch_bounds__(256, 1)
moe_gemm_imma(const float* __restrict__ be, float* __restrict__ out) {
    const int e = blockIdx.z;
    const int cnt = d_cnt[e];
    const int m0 = blockIdx.y * BM;
    if (m0 >= cnt) return;
    const int n0 = blockIdx.x * BN;

    extern __shared__ char smem[];
    const uint32_t sb = smem_u32(smem);
    const int tid  = threadIdx.x;
    const int wid  = tid >> 5;
    const int lane = tid & 31;
    const int wm   = wid >> 2;       // 0..1  (m: 64 each)
    const int wn   = wid & 3;        // 0..3  (n: 32 each)

    int*   sTok  = (int*)smem;
    float* sGate = (float*)(smem + 512);
    float* sScA  = (float*)(smem + 1024);

    if (tid < BM) {
        int r = m0 + tid;
        if (r < cnt) {
            int tk = d_list[e * T_TOK + r];
            sTok[tid] = tk; sGate[tid] = d_gatev[e * T_TOK + r]; sScA[tid] = d_xscale[tk];
        } else {
            sTok[tid] = 0; sGate[tid] = 0.f; sScA[tid] = 0.f;
        }
    }
    __syncthreads();

    // --- gmem gather sources (per thread; constant across chunks) ---
    const int row2 = tid >> 1;           // 0..127 tile row
    const int half = tid & 1;            // which 64B half of the 128B row
    uint32_t sD[4];
#pragma unroll
    for (int i = 0; i < 4; i++) {
        uint32_t o = row2 * 128 + (half * 4 + i) * 16;
        sD[i] = o ^ ((o >> 3) & 0x70);   // SW128
    }
    const signed char* aQ1 = d_xq1 + (size_t)sTok[row2] * HDIM + half * 64;
    const signed char* aQ2 = d_xq2 + (size_t)sTok[row2] * HDIM + half * 64;
    const signed char* bQ1 = d_wq1 + ((size_t)e * HDIM + n0 + row2) * HDIM + half * 64;
    const signed char* bQ2 = d_wq2 + ((size_t)e * HDIM + n0 + row2) * HDIM + half * 64;

#define ISSUE_CHUNK(stage, k0)                                            \
    {                                                                     \
        _Pragma("unroll")                                                 \
        for (int i = 0; i < 4; i++) {                                     \
            cp16((stage) + A_Q1_OFF + sD[i], aQ1 + (k0) + i * 16);        \
            cp16((stage) + A_Q2_OFF + sD[i], aQ2 + (k0) + i * 16);        \
            cp16((stage) + B_Q1_OFF + sD[i], bQ1 + (k0) + i * 16);        \
            cp16((stage) + B_Q2_OFF + sD[i], bQ2 + (k0) + i * 16);        \
        }                                                                 \
        asm volatile("cp.async.commit_group;" ::: "memory");              \
    }

    // --- ldmatrix addressing (per lane) ---
    uint32_t aRow[4], bRow[2];
#pragma unroll
    for (int mi = 0; mi < 4; mi++) aRow[mi] = wm * 64 + mi * 16 + (lane & 15);
#pragma unroll
    for (int j = 0; j < 2; j++)    bRow[j]  = wn * 32 + j * 16 + (lane & 15);
    const uint32_t kcHalf = (lane >> 4);   // which 16B chunk of the k32

    int acc1[4][4][4], acc2[4][4][4];
#pragma unroll
    for (int mi = 0; mi < 4; mi++)
#pragma unroll
        for (int nj = 0; nj < 4; nj++)
#pragma unroll
            for (int q = 0; q < 4; q++) { acc1[mi][nj][q] = 0; acc2[mi][nj][q] = 0; }

    const uint32_t stgBase = sb + SM_HDR;

    // prologue: fill 3 stages
    ISSUE_CHUNK(stgBase + 0 * STAGE_BYTES, 0);
    ISSUE_CHUNK(stgBase + 1 * STAGE_BYTES, BKC);
    ISSUE_CHUNK(stgBase + 2 * STAGE_BYTES, 2 * BKC);

    int sidx = 0;
    for (int c = 0; c < NCHUNK; c++) {
        asm volatile("cp.async.wait_group 2;" ::: "memory");
        __syncthreads();
        const uint32_t stage = stgBase + sidx * STAGE_BYTES;

#pragma unroll
        for (int ks = 0; ks < 4; ks++) {              // k32 step within k128 chunk
            const uint32_t kc = ks * 2 + kcHalf;      // 16B unit index 0..7
            uint32_t a1[4][4], a2[4][4];
#pragma unroll
            for (int mi = 0; mi < 4; mi++) {
                uint32_t off = aRow[mi] * 128 + ((kc ^ (aRow[mi] & 7)) << 4);
                ldm4(stage + A_Q1_OFF + off, a1[mi][0], a1[mi][1], a1[mi][2], a1[mi][3]);
                ldm4(stage + A_Q2_OFF + off, a2[mi][0], a2[mi][1], a2[mi][2], a2[mi][3]);
            }
            uint32_t b1[2][4], b2[2][4];
#pragma unroll
            for (int j = 0; j < 2; j++) {
                uint32_t off = bRow[j] * 128 + ((kc ^ (bRow[j] & 7)) << 4);
                ldm4(stage + B_Q1_OFF + off, b1[j][0], b1[j][1], b1[j][2], b1[j][3]);
                ldm4(stage + B_Q2_OFF + off, b2[j][0], b2[j][1], b2[j][2], b2[j][3]);
            }
#pragma unroll
            for (int mi = 0; mi < 4; mi++) {
#pragma unroll
                for (int nj = 0; nj < 4; nj++) {
                    const int j = nj >> 1, h = nj & 1;
                    imma16832(acc1[mi][nj], a1[mi], b1[j][h], b1[j][h + 2]);  // a1*b1
                    imma16832(acc2[mi][nj], a1[mi], b2[j][h], b2[j][h + 2]);  // a1*b2
                    imma16832(acc2[mi][nj], a2[mi], b1[j][h], b1[j][h + 2]);  // a2*b1
                }
            }
        }

        __syncthreads();
        if (c + NSTAGE < NCHUNK) {
            ISSUE_CHUNK(stage, (c + NSTAGE) * BKC);
        } else {
            asm volatile("cp.async.commit_group;" ::: "memory");
        }
        sidx = (sidx == NSTAGE - 1) ? 0 : sidx + 1;
    }

    // --- epilogue: out[tok] += gate * (sA*sB*(acc1 + acc2/128) + be) ---
    const float* beg = be + (size_t)e * HDIM + n0;
    const float* wsg = d_wscale + (size_t)e * HDIM + n0;
    const int cl = (lane & 3) * 2;
    const int rl = lane >> 2;
#pragma unroll
    for (int mi = 0; mi < 4; mi++) {
        const int r0 = wm * 64 + mi * 16 + rl;
        const int r1 = r0 + 8;
        const bool v0 = (m0 + r0) < cnt;
        const bool v1 = (m0 + r1) < cnt;
        const int   t0 = sTok[r0], t1 = sTok[r1];
        const float g0 = sGate[r0], g1 = sGate[r1];
        const float sA0 = sScA[r0], sA1 = sScA[r1];
        float* o0 = out + (size_t)t0 * HDIM + n0;
        float* o1 = out + (size_t)t1 * HDIM + n0;
#pragma unroll
        for (int nj = 0; nj < 4; nj++) {
            const int col = wn * 32 + nj * 8 + cl;
            const float sB0 = wsg[col], sB1 = wsg[col + 1];
            const float b0 = beg[col],  b1v = beg[col + 1];
            if (v0) {
                float d00 = sA0 * sB0 * ((float)acc1[mi][nj][0] + (float)acc2[mi][nj][0] * 0.0078125f);
                float d01 = sA0 * sB1 * ((float)acc1[mi][nj][1] + (float)acc2[mi][nj][1] * 0.0078125f);
                atomicAdd(&o0[col],     g0 * (d00 + b0));
                atomicAdd(&o0[col + 1], g0 * (d01 + b1v));
            }
            if (v1) {
                float d10 = sA1 * sB0 * ((float)acc1[mi][nj][2] + (float)acc2[mi][nj][2] * 0.0078125f);
                float d11 = sA1 * sB1 * ((float)acc1[mi][nj][3] + (float)acc2[mi][nj][3] * 0.0078125f);
                atomicAdd(&o1[col],     g1 * (d10 + b0));
                atomicAdd(&o1[col + 1], g1 * (d11 + b1v));
            }
        }
    }
}

// ---------------------------------------------------------------------------
extern "C" void kernel_launch(void* const* d_in, const int* in_sizes, int n_in,
                              void* d_out, int out_size) {
    const float* x  = (const float*)d_in[0];
    const float* Wg = (const float*)d_in[1];
    const float* bg = (const float*)d_in[2];
    const float* We = (const float*)d_in[3];
    const float* be = (const float*)d_in[4];
    float* out = (float*)d_out;

    cudaFuncSetAttribute(moe_gemm_imma, cudaFuncAttributeMaxDynamicSharedMemorySize, SMEM_TOTAL);

    init_kernel<<<1024, 256>>>(out);
    quant_x<<<T_TOK / 8, 256>>>(x);
    dim3 cg(HDIM / 256, NEXP);
    colmax_w<<<cg, 256>>>(We);
    dim3 tg(HDIM / 32, HDIM / 32, NEXP);
    quant_w<<<tg, 256>>>(We);
    router_kernel<<<T_TOK / 8, 256>>>(x, Wg, bg);

    dim3 grid(HDIM / BN, T_TOK / BM, NEXP);
    moe_gemm_imma<<<grid, 256, SMEM_TOTAL>>>(be, out);
}

// round 9
// speedup vs baseline: 3.1584x; 3.1584x over previous
#include <cuda_runtime.h>
#include <cuda_fp16.h>
#include <cstdint>

#define T_TOK 8192
#define HDIM  2048
#define NEXP  8

// GEMM tile config (fp16 single-term mma.sync path)
#define BM 128
#define BN 128
#define BKC 64                     // K elems per chunk = 128B fp16 rows (SW128)
#define NCHUNK (HDIM / BKC)        // 32
#define NSTAGE 4
#define A_OFF 0
#define B_OFF 16384
#define STAGE_BYTES 32768
#define SM_HDR 1024
#define SMEM_TOTAL (SM_HDR + NSTAGE * STAGE_BYTES)   // 132096

// ---------------- device scratch (no allocations allowed) -------------------
__device__ int    d_cnt[NEXP];
__device__ int    d_list[NEXP * T_TOK];
__device__ float  d_gatev[NEXP * T_TOK];
__device__ __half d_xh[(size_t)T_TOK * HDIM];
__device__ __half d_wth[(size_t)NEXP * HDIM * HDIM];   // We^T [e][n][k]

// ---------------- helpers ---------------------------------------------------
__device__ __forceinline__ uint32_t smem_u32(const void* p) {
    uint32_t a;
    asm("{ .reg .u64 t; cvta.to.shared.u64 t, %1; cvt.u32.u64 %0, t; }" : "=r"(a) : "l"(p));
    return a;
}
__device__ __forceinline__ void cp16(uint32_t dst, const void* src) {
    asm volatile("cp.async.cg.shared.global [%0], [%1], 16;" :: "r"(dst), "l"(src));
}
__device__ __forceinline__ void ldm4(uint32_t addr, uint32_t& r0, uint32_t& r1,
                                     uint32_t& r2, uint32_t& r3) {
    asm volatile("ldmatrix.sync.aligned.m8n8.x4.shared.b16 {%0,%1,%2,%3}, [%4];"
                 : "=r"(r0), "=r"(r1), "=r"(r2), "=r"(r3) : "r"(addr));
}
__device__ __forceinline__ void mma16816(float* c, const uint32_t* a,
                                         uint32_t b0, uint32_t b1) {
    asm volatile(
        "mma.sync.aligned.m16n8k16.row.col.f32.f16.f16.f32 "
        "{%0,%1,%2,%3}, {%4,%5,%6,%7}, {%8,%9}, {%0,%1,%2,%3};"
        : "+f"(c[0]), "+f"(c[1]), "+f"(c[2]), "+f"(c[3])
        : "r"(a[0]), "r"(a[1]), "r"(a[2]), "r"(a[3]), "r"(b0), "r"(b1));
}

// ---------------- kernel 0: init --------------------------------------------
__global__ void init_kernel(float* __restrict__ out) {
    int i = blockIdx.x * blockDim.x + threadIdx.x;
    if (i < NEXP) d_cnt[i] = 0;
    const int n4 = (T_TOK * HDIM) / 4;
    float4 z = make_float4(0.f, 0.f, 0.f, 0.f);
    float4* o4 = (float4*)out;
    for (int j = i; j < n4; j += gridDim.x * blockDim.x) o4[j] = z;
}

// ---------------- kernel 1: convert x to fp16 --------------------------------
__global__ void convert_x(const float* __restrict__ x) {
    int n = (T_TOK * HDIM) / 4;
    const float4* x4 = (const float4*)x;
    for (int i = blockIdx.x * blockDim.x + threadIdx.x; i < n; i += gridDim.x * blockDim.x) {
        float4 v = x4[i];
        __half2 h0 = __floats2half2_rn(v.x, v.y);
        __half2 h1 = __floats2half2_rn(v.z, v.w);
        ((__half2*)d_xh)[2 * i]     = h0;
        ((__half2*)d_xh)[2 * i + 1] = h1;
    }
}

// ---------------- kernel 2: transpose + convert We ---------------------------
__global__ void transpose_we(const float* __restrict__ We) {
    __shared__ float tile[32][33];
    int e = blockIdx.z;
    int n0 = blockIdx.x * 32, k0 = blockIdx.y * 32;
    int tx = threadIdx.x & 31, ty = threadIdx.x >> 5;   // 32 x 8
    const float* src = We + ((size_t)e * HDIM + k0) * HDIM + n0;
#pragma unroll
    for (int i = 0; i < 4; i++)
        tile[ty + 8 * i][tx] = src[(size_t)(ty + 8 * i) * HDIM + tx];
    __syncthreads();
    size_t ob = ((size_t)e * HDIM + n0) * HDIM + k0;
#pragma unroll
    for (int i = 0; i < 4; i++)
        d_wth[ob + (size_t)(ty + 8 * i) * HDIM + tx] = __float2half_rn(tile[tx][ty + 8 * i]);
}

// ---------------- kernel 3: router (warp per token, lane-stride reads) -------
__global__ void router_kernel(const float* __restrict__ x,
                              const float* __restrict__ Wg,
                              const float* __restrict__ bg) {
    const int wid_g = (blockIdx.x * blockDim.x + threadIdx.x) >> 5;
    if (wid_g >= T_TOK) return;
    const int lane = threadIdx.x & 31;
    const int t = wid_g;

    float acc[NEXP];
#pragma unroll
    for (int e = 0; e < NEXP; e++) acc[e] = 0.f;

    const float* xr = x + (size_t)t * HDIM;
#pragma unroll 4
    for (int j = 0; j < HDIM / 32; j++) {
        const int h = lane + 32 * j;
        const float xs = xr[h];                 // 4B stride across lanes: 1 line
        const float4* wr = (const float4*)(Wg + (size_t)h * NEXP);
        float4 w0 = wr[0], w1 = wr[1];          // 32B per lane: 8 lines, L1-hot
        acc[0] += xs * w0.x; acc[1] += xs * w0.y; acc[2] += xs * w0.z; acc[3] += xs * w0.w;
        acc[4] += xs * w1.x; acc[5] += xs * w1.y; acc[6] += xs * w1.z; acc[7] += xs * w1.w;
    }
#pragma unroll
    for (int e = 0; e < NEXP; e++) {
#pragma unroll
        for (int s = 16; s > 0; s >>= 1)
            acc[e] += __shfl_xor_sync(0xFFFFFFFFu, acc[e], s);
    }
    if (lane == 0) {
#pragma unroll
        for (int e = 0; e < NEXP; e++) acc[e] += bg[e];
        float m = acc[0];
#pragma unroll
        for (int e = 1; e < NEXP; e++) m = fmaxf(m, acc[e]);
        float p[NEXP], s = 0.f;
#pragma unroll
        for (int e = 0; e < NEXP; e++) { p[e] = __expf(acc[e] - m); s += p[e]; }
        float inv = 1.f / s;
#pragma unroll
        for (int e = 0; e < NEXP; e++) p[e] *= inv;
        int i0 = 0;
#pragma unroll
        for (int e = 1; e < NEXP; e++) if (p[e] > p[i0]) i0 = e;
        int i1 = (i0 == 0) ? 1 : 0;
#pragma unroll
        for (int e = 0; e < NEXP; e++) if (e != i0 && p[e] > p[i1]) i1 = e;
        int pos0 = atomicAdd(&d_cnt[i0], 1);
        d_list[i0 * T_TOK + pos0] = t;  d_gatev[i0 * T_TOK + pos0] = p[i0];
        int pos1 = atomicAdd(&d_cnt[i1], 1);
        d_list[i1 * T_TOK + pos1] = t;  d_gatev[i1 * T_TOK + pos1] = p[i1];
    }
}

// ---------------- kernel 4: grouped GEMM via fp16 mma.sync (1 term) ----------
__global__ void __launch_bounds__(256, 1)
moe_gemm_mma(const float* __restrict__ be, float* __restrict__ out) {
    const int e = blockIdx.z;
    const int cnt = d_cnt[e];
    const int m0 = blockIdx.y * BM;
    if (m0 >= cnt) return;
    const int n0 = blockIdx.x * BN;

    extern __shared__ char smem[];
    const uint32_t sb = smem_u32(smem);
    const int tid  = threadIdx.x;
    const int wid  = tid >> 5;
    const int lane = tid & 31;
    const int wm   = wid >> 2;       // 0..1  (m: 64 each)
    const int wn   = wid & 3;        // 0..3  (n: 32 each)

    int*   sTok  = (int*)smem;
    float* sGate = (float*)(smem + 512);

    if (tid < BM) {
        int r = m0 + tid;
        if (r < cnt) { sTok[tid] = d_list[e * T_TOK + r]; sGate[tid] = d_gatev[e * T_TOK + r]; }
        else         { sTok[tid] = 0;                      sGate[tid] = 0.f; }
    }
    __syncthreads();

    // --- gmem gather sources (per thread; constant across chunks) ---
    const int row2 = tid >> 1;           // 0..127
    const int half = tid & 1;            // 64B half of the 128B row
    uint32_t sD[4];
#pragma unroll
    for (int i = 0; i < 4; i++) {
        uint32_t o = row2 * 128 + (half * 4 + i) * 16;
        sD[i] = o ^ ((o >> 3) & 0x70);   // SW128
    }
    const __half* aS = d_xh  + (size_t)sTok[row2] * HDIM + half * 32;
    const __half* bS = d_wth + ((size_t)e * HDIM + n0 + row2) * HDIM + half * 32;

#define ISSUE_CHUNK(stage, k0)                                            \
    {                                                                     \
        _Pragma("unroll")                                                 \
        for (int i = 0; i < 4; i++) {                                     \
            cp16((stage) + A_OFF + sD[i], aS + (k0) + i * 8);             \
            cp16((stage) + B_OFF + sD[i], bS + (k0) + i * 8);             \
        }                                                                 \
        asm volatile("cp.async.commit_group;" ::: "memory");              \
    }

    // --- ldmatrix addressing (per lane) ---
    uint32_t aRow[4], bRow[2];
#pragma unroll
    for (int mi = 0; mi < 4; mi++) aRow[mi] = wm * 64 + mi * 16 + (lane & 15);
#pragma unroll
    for (int j = 0; j < 2; j++)    bRow[j]  = wn * 32 + j * 16 + (lane & 15);
    const uint32_t kcHalf = (lane >> 4);   // which 16B chunk of the k16

    float acc[4][4][4];
#pragma unroll
    for (int mi = 0; mi < 4; mi++)
#pragma unroll
        for (int nj = 0; nj < 4; nj++)
#pragma unroll
            for (int q = 0; q < 4; q++) acc[mi][nj][q] = 0.f;

    const uint32_t stgBase = sb + SM_HDR;

    // prologue: fill 4 stages
    ISSUE_CHUNK(stgBase + 0 * STAGE_BYTES, 0);
    ISSUE_CHUNK(stgBase + 1 * STAGE_BYTES, BKC);
    ISSUE_CHUNK(stgBase + 2 * STAGE_BYTES, 2 * BKC);
    ISSUE_CHUNK(stgBase + 3 * STAGE_BYTES, 3 * BKC);

    int sidx = 0;
    for (int c = 0; c < NCHUNK; c++) {
        asm volatile("cp.async.wait_group 3;" ::: "memory");
        __syncthreads();
        const uint32_t stage = stgBase + sidx * STAGE_BYTES;

#pragma unroll
        for (int ks = 0; ks < 4; ks++) {
            const uint32_t kc = ks * 2 + kcHalf;
            uint32_t a[4][4];
#pragma unroll
            for (int mi = 0; mi < 4; mi++) {
                uint32_t off = aRow[mi] * 128 + ((kc ^ (aRow[mi] & 7)) << 4);
                ldm4(stage + A_OFF + off, a[mi][0], a[mi][1], a[mi][2], a[mi][3]);
            }
            uint32_t b[2][4];
#pragma unroll
            for (int j = 0; j < 2; j++) {
                uint32_t off = bRow[j] * 128 + ((kc ^ (bRow[j] & 7)) << 4);
                ldm4(stage + B_OFF + off, b[j][0], b[j][1], b[j][2], b[j][3]);
            }
#pragma unroll
            for (int mi = 0; mi < 4; mi++) {
#pragma unroll
                for (int nj = 0; nj < 4; nj++) {
                    const int j = nj >> 1, h = nj & 1;
                    mma16816(acc[mi][nj], a[mi], b[j][h], b[j][h + 2]);
                }
            }
        }

        __syncthreads();
        if (c + NSTAGE < NCHUNK) {
            ISSUE_CHUNK(stage, (c + NSTAGE) * BKC);
        } else {
            asm volatile("cp.async.commit_group;" ::: "memory");
        }
        sidx = (sidx == NSTAGE - 1) ? 0 : sidx + 1;
    }

    // --- epilogue: out[tok] += gate * (acc + be[e]) ---
    const float* beg = be + (size_t)e * HDIM + n0;
    const int cl = (lane & 3) * 2;
    const int rl = lane >> 2;
#pragma unroll
    for (int mi = 0; mi < 4; mi++) {
        const int r0 = wm * 64 + mi * 16 + rl;
        const int r1 = r0 + 8;
        const bool v0 = (m0 + r0) < cnt;
        const bool v1 = (m0 + r1) < cnt;
        const int   t0 = sTok[r0], t1 = sTok[r1];
        const float g0 = sGate[r0], g1 = sGate[r1];
        float* o0 = out + (size_t)t0 * HDIM + n0;
        float* o1 = out + (size_t)t1 * HDIM + n0;
#pragma unroll
        for (int nj = 0; nj < 4; nj++) {
            const int col = wn * 32 + nj * 8 + cl;
            const float b0 = beg[col], b1 = beg[col + 1];
            if (v0) {
                atomicAdd(&o0[col],     g0 * (acc[mi][nj][0] + b0));
                atomicAdd(&o0[col + 1], g0 * (acc[mi][nj][1] + b1));
            }
            if (v1) {
                atomicAdd(&o1[col],     g1 * (acc[mi][nj][2] + b0));
                atomicAdd(&o1[col + 1], g1 * (acc[mi][nj][3] + b1));
            }
        }
    }
}

// ---------------------------------------------------------------------------
extern "C" void kernel_launch(void* const* d_in, const int* in_sizes, int n_in,
                              void* d_out, int out_size) {
    const float* x  = (const float*)d_in[0];
    const float* Wg = (const float*)d_in[1];
    const float* bg = (const float*)d_in[2];
    const float* We = (const float*)d_in[3];
    const float* be = (const float*)d_in[4];
    float* out = (float*)d_out;

    cudaFuncSetAttribute(moe_gemm_mma, cudaFuncAttributeMaxDynamicSharedMemorySize, SMEM_TOTAL);

    init_kernel<<<1024, 256>>>(out);
    convert_x<<<2048, 256>>>(x);
    dim3 tg(HDIM / 32, HDIM / 32, NEXP);
    transpose_we<<<tg, 256>>>(We);
    router_kernel<<<T_TOK / 8, 256>>>(x, Wg, bg);

    dim3 grid(HDIM / BN, T_TOK / BM, NEXP);
    moe_gemm_mma<<<grid, 256, SMEM_TOTAL>>>(be, out);
}

// round 10
// speedup vs baseline: 6.1741x; 1.9548x over previous
#include <cuda_runtime.h>
#include <cuda_fp16.h>
#include <cstdint>

#define T_TOK 8192
#define HDIM  2048
#define NEXP  8

// GEMM tile config (fp16 mma.sync; B via cp.async.bulk from pre-swizzled gmem)
#define BM 128
#define BN 256
#define BKC 64                     // K elems per chunk (128B fp16 rows, SW128)
#define NCHUNK (HDIM / BKC)        // 32
#define NSTAGE 3
#define A_OFF 0                    // 16 KB (128 rows x 128B)
#define B_OFF 16384                // 32 KB (256 rows x 128B)
#define STAGE_BYTES 49152
#define SM_HDR 1024
#define SMEM_TOTAL (SM_HDR + NSTAGE * STAGE_BYTES)   // 148480
#define B_BLOCK_BYTES 32768
#define B_BLOCK_HALVES 16384

// ---------------- device scratch (no allocations allowed) -------------------
__device__ int    d_cnt[NEXP];
__device__ int    d_list[NEXP * T_TOK];
__device__ float  d_gatev[NEXP * T_TOK];
__device__ __half d_xh[(size_t)T_TOK * HDIM];
// We^T pre-swizzled tile layout: block[(e*8+nt)*32+c] of 32KB, inside:
// swz128(row*128 + (kk>>3)*16) + (kk&7)*2  for n=nt*256+row, k=c*64+kk
__device__ __half d_wtile[(size_t)NEXP * HDIM * HDIM];

// ---------------- helpers ---------------------------------------------------
__device__ __forceinline__ uint32_t smem_u32(const void* p) {
    uint32_t a;
    asm("{ .reg .u64 t; cvta.to.shared.u64 t, %1; cvt.u32.u64 %0, t; }" : "=r"(a) : "l"(p));
    return a;
}
__device__ __forceinline__ uint32_t swz128(uint32_t o) { return o ^ ((o >> 3) & 0x70); }
__device__ __forceinline__ void cp16(uint32_t dst, const void* src) {
    asm volatile("cp.async.cg.shared.global [%0], [%1], 16;" :: "r"(dst), "l"(src));
}
__device__ __forceinline__ void ldm4(uint32_t addr, uint32_t& r0, uint32_t& r1,
                                     uint32_t& r2, uint32_t& r3) {
    asm volatile("ldmatrix.sync.aligned.m8n8.x4.shared.b16 {%0,%1,%2,%3}, [%4];"
                 : "=r"(r0), "=r"(r1), "=r"(r2), "=r"(r3) : "r"(addr));
}
__device__ __forceinline__ void mma16816(float* c, const uint32_t* a,
                                         uint32_t b0, uint32_t b1) {
    asm volatile(
        "mma.sync.aligned.m16n8k16.row.col.f32.f16.f16.f32 "
        "{%0,%1,%2,%3}, {%4,%5,%6,%7}, {%8,%9}, {%0,%1,%2,%3};"
        : "+f"(c[0]), "+f"(c[1]), "+f"(c[2]), "+f"(c[3])
        : "r"(a[0]), "r"(a[1]), "r"(a[2]), "r"(a[3]), "r"(b0), "r"(b1));
}
__device__ __forceinline__ void mbar_init(uint32_t a, uint32_t cnt) {
    asm volatile("mbarrier.init.shared.b64 [%0], %1;" :: "r"(a), "r"(cnt) : "memory");
}
__device__ __forceinline__ void mbar_expect_tx(uint32_t a, uint32_t tx) {
    asm volatile("mbarrier.arrive.expect_tx.shared.b64 _, [%0], %1;"
                 :: "r"(a), "r"(tx) : "memory");
}
__device__ __forceinline__ void mbar_wait(uint32_t a, uint32_t ph) {
    asm volatile(
        "{\n\t.reg .pred P;\n\tWL_%=:\n\t"
        "mbarrier.try_wait.parity.acquire.cta.shared::cta.b64 P, [%0], %1, 0x989680;\n\t"
        "@P bra.uni WD_%=;\n\tbra.uni WL_%=;\n\tWD_%=:\n\t}"
        :: "r"(a), "r"(ph) : "memory");
}
__device__ __forceinline__ void bulk_ld(uint32_t dst, const void* src,
                                        uint32_t bytes, uint32_t mbar) {
    asm volatile("cp.async.bulk.shared::cta.global.mbarrier::complete_tx::bytes "
                 "[%0], [%1], %2, [%3];"
                 :: "r"(dst), "l"(src), "r"(bytes), "r"(mbar) : "memory");
}

// ---------------- kernel 0: init --------------------------------------------
__global__ void init_kernel(float* __restrict__ out) {
    int i = blockIdx.x * blockDim.x + threadIdx.x;
    if (i < NEXP) d_cnt[i] = 0;
    const int n4 = (T_TOK * HDIM) / 4;
    float4 z = make_float4(0.f, 0.f, 0.f, 0.f);
    float4* o4 = (float4*)out;
    for (int j = i; j < n4; j += gridDim.x * blockDim.x) o4[j] = z;
}

// ---------------- kernel 1: convert x to fp16 --------------------------------
__global__ void convert_x(const float* __restrict__ x) {
    int n = (T_TOK * HDIM) / 4;
    const float4* x4 = (const float4*)x;
    for (int i = blockIdx.x * blockDim.x + threadIdx.x; i < n; i += gridDim.x * blockDim.x) {
        float4 v = x4[i];
        ((__half2*)d_xh)[2 * i]     = __floats2half2_rn(v.x, v.y);
        ((__half2*)d_xh)[2 * i + 1] = __floats2half2_rn(v.z, v.w);
    }
}

// ---------------- kernel 2: transpose + convert We into swizzled tiles -------
__global__ void transpose_we(const float* __restrict__ We) {
    __shared__ float tile[32][33];
    int e = blockIdx.z;
    int n0 = blockIdx.x * 32, k0 = blockIdx.y * 32;
    int tx = threadIdx.x & 31, ty = threadIdx.x >> 5;   // 32 x 8
    const float* src = We + ((size_t)e * HDIM + k0) * HDIM + n0;
#pragma unroll
    for (int i = 0; i < 4; i++)
        tile[ty + 8 * i][tx] = src[(size_t)(ty + 8 * i) * HDIM + tx];
    __syncthreads();
    const int k  = k0 + tx;           // element k index
    const int c  = k >> 6;            // k-chunk
    const int kk = k & 63;            // within chunk
    const uint32_t kbyte = ((kk >> 3) << 4) + (kk & 7) * 2;
#pragma unroll
    for (int i = 0; i < 4; i++) {
        const int n   = n0 + ty + 8 * i;
        const int nt  = n >> 8;
        const int row = n & 255;
        size_t block = ((size_t)(e * 8 + nt) * 32 + c) * B_BLOCK_BYTES;
        uint32_t off = swz128(row * 128 + kbyte & ~15u) + (kbyte & 15u);
        // swizzle operates on 16B-chunk bits only; recompute cleanly:
        off = swz128((uint32_t)(row * 128 + ((kk >> 3) << 4))) + (kk & 7) * 2;
        *(__half*)((char*)d_wtile + block + off) = __float2half_rn(tile[tx][ty + 8 * i]);
    }
}

// ---------------- kernel 3: router (warp per token) --------------------------
__global__ void router_kernel(const float* __restrict__ x,
                              const float* __restrict__ Wg,
                              const float* __restrict__ bg) {
    const int wid_g = (blockIdx.x * blockDim.x + threadIdx.x) >> 5;
    if (wid_g >= T_TOK) return;
    const int lane = threadIdx.x & 31;
    const int t = wid_g;

    float acc[NEXP];
#pragma unroll
    for (int e = 0; e < NEXP; e++) acc[e] = 0.f;

    const float* xr = x + (size_t)t * HDIM;
#pragma unroll 4
    for (int j = 0; j < HDIM / 32; j++) {
        const int h = lane + 32 * j;
        const float xs = xr[h];
        const float4* wr = (const float4*)(Wg + (size_t)h * NEXP);
        float4 w0 = wr[0], w1 = wr[1];
        acc[0] += xs * w0.x; acc[1] += xs * w0.y; acc[2] += xs * w0.z; acc[3] += xs * w0.w;
        acc[4] += xs * w1.x; acc[5] += xs * w1.y; acc[6] += xs * w1.z; acc[7] += xs * w1.w;
    }
#pragma unroll
    for (int e = 0; e < NEXP; e++) {
#pragma unroll
        for (int s = 16; s > 0; s >>= 1)
            acc[e] += __shfl_xor_sync(0xFFFFFFFFu, acc[e], s);
    }
    if (lane == 0) {
#pragma unroll
        for (int e = 0; e < NEXP; e++) acc[e] += bg[e];
        float m = acc[0];
#pragma unroll
        for (int e = 1; e < NEXP; e++) m = fmaxf(m, acc[e]);
        float p[NEXP], s = 0.f;
#pragma unroll
        for (int e = 0; e < NEXP; e++) { p[e] = __expf(acc[e] - m); s += p[e]; }
        float inv = 1.f / s;
#pragma unroll
        for (int e = 0; e < NEXP; e++) p[e] *= inv;
        int i0 = 0;
#pragma unroll
        for (int e = 1; e < NEXP; e++) if (p[e] > p[i0]) i0 = e;
        int i1 = (i0 == 0) ? 1 : 0;
#pragma unroll
        for (int e = 0; e < NEXP; e++) if (e != i0 && p[e] > p[i1]) i1 = e;
        int pos0 = atomicAdd(&d_cnt[i0], 1);
        d_list[i0 * T_TOK + pos0] = t;  d_gatev[i0 * T_TOK + pos0] = p[i0];
        int pos1 = atomicAdd(&d_cnt[i1], 1);
        d_list[i1 * T_TOK + pos1] = t;  d_gatev[i1 * T_TOK + pos1] = p[i1];
    }
}

// ---------------- kernel 4: grouped GEMM, A via cp.async, B via bulk ---------
__global__ void __launch_bounds__(256, 1)
moe_gemm_mma(const float* __restrict__ be, float* __restrict__ out) {
    const int e = blockIdx.z;
    const int cnt = d_cnt[e];
    const int m0 = blockIdx.y * BM;
    if (m0 >= cnt) return;
    const int nt = blockIdx.x;          // n-tile (256 wide)
    const int n0 = nt * BN;

    extern __shared__ char smem[];
    const uint32_t sb = smem_u32(smem);
    const int tid  = threadIdx.x;
    const int wid  = tid >> 5;
    const int lane = tid & 31;
    const int wm   = wid >> 2;       // 0..1  (m: 64 each)
    const int wn   = wid & 3;        // 0..3  (n: 64 each)

    int*   sTok  = (int*)smem;
    float* sGate = (float*)(smem + 512);
    const uint32_t mbar0 = sb + 960;    // 3 mbarriers at 960, 968, 976

    if (tid == 0) {
#pragma unroll
        for (int s = 0; s < NSTAGE; s++) mbar_init(mbar0 + 8 * s, 1);
    }
    if (tid < BM) {
        int r = m0 + tid;
        if (r < cnt) { sTok[tid] = d_list[e * T_TOK + r]; sGate[tid] = d_gatev[e * T_TOK + r]; }
        else         { sTok[tid] = 0;                      sGate[tid] = 0.f; }
    }
    asm volatile("fence.proxy.async.shared::cta;" ::: "memory");
    __syncthreads();

    // --- A gather sources (per thread) ---
    const int row2 = tid >> 1;           // 0..127
    const int half = tid & 1;
    uint32_t sD[4];
#pragma unroll
    for (int i = 0; i < 4; i++) {
        uint32_t o = row2 * 128 + (half * 4 + i) * 16;
        sD[i] = swz128(o);
    }
    const __half* aS = d_xh + (size_t)sTok[row2] * HDIM + half * 32;
    // B blocks for this (e, nt): 32 consecutive 32KB blocks
    const char* bBase = (const char*)d_wtile + ((size_t)(e * 8 + nt) * 32) * B_BLOCK_BYTES;

    const uint32_t stgBase = sb + SM_HDR;

#define ISSUE_CHUNK(sidx_, c_)                                                \
    {                                                                         \
        const uint32_t stg_ = stgBase + (sidx_) * STAGE_BYTES;                \
        if (tid == 0) {                                                       \
            mbar_expect_tx(mbar0 + 8 * (sidx_), B_BLOCK_BYTES);               \
            bulk_ld(stg_ + B_OFF, bBase + (size_t)(c_) * B_BLOCK_BYTES,       \
                    B_BLOCK_BYTES, mbar0 + 8 * (sidx_));                      \
        }                                                                     \
        _Pragma("unroll")                                                     \
        for (int i = 0; i < 4; i++)                                           \
            cp16(stg_ + A_OFF + sD[i], aS + (c_) * BKC + i * 8);              \
        asm volatile("cp.async.commit_group;" ::: "memory");                  \
    }

    // --- ldmatrix addressing ---
    uint32_t aRow[4], bRow[4];
#pragma unroll
    for (int mi = 0; mi < 4; mi++) aRow[mi] = wm * 64 + mi * 16 + (lane & 15);
#pragma unroll
    for (int j = 0; j < 4; j++)    bRow[j]  = wn * 64 + j * 16 + (lane & 15);
    const uint32_t kcHalf = (lane >> 4);

    float acc[4][8][4];
#pragma unroll
    for (int mi = 0; mi < 4; mi++)
#pragma unroll
        for (int nj = 0; nj < 8; nj++)
#pragma unroll
            for (int q = 0; q < 4; q++) acc[mi][nj][q] = 0.f;

    // prologue: fill 3 stages
    ISSUE_CHUNK(0, 0);
    ISSUE_CHUNK(1, 1);
    ISSUE_CHUNK(2, 2);

    int sidx = 0;
    for (int c = 0; c < NCHUNK; c++) {
        asm volatile("cp.async.wait_group 2;" ::: "memory");
        mbar_wait(mbar0 + 8 * sidx, (c / NSTAGE) & 1);
        __syncthreads();
        const uint32_t stage = stgBase + sidx * STAGE_BYTES;

#pragma unroll
        for (int ks = 0; ks < 4; ks++) {
            const uint32_t kc = ks * 2 + kcHalf;
            uint32_t a[4][4];
#pragma unroll
            for (int mi = 0; mi < 4; mi++) {
                uint32_t off = aRow[mi] * 128 + ((kc ^ (aRow[mi] & 7)) << 4);
                ldm4(stage + A_OFF + off, a[mi][0], a[mi][1], a[mi][2], a[mi][3]);
            }
            uint32_t b[4][4];
#pragma unroll
            for (int j = 0; j < 4; j++) {
                uint32_t off = bRow[j] * 128 + ((kc ^ (bRow[j] & 7)) << 4);
                ldm4(stage + B_OFF + off, b[j][0], b[j][1], b[j][2], b[j][3]);
            }
#pragma unroll
            for (int mi = 0; mi < 4; mi++) {
#pragma unroll
                for (int nj = 0; nj < 8; nj++) {
                    const int j = nj >> 1, h = nj & 1;
                    mma16816(acc[mi][nj], a[mi], b[j][h], b[j][h + 2]);
                }
            }
        }

        __syncthreads();
        if (c + NSTAGE < NCHUNK) {
            ISSUE_CHUNK(sidx, c + NSTAGE);
        } else {
            asm volatile("cp.async.commit_group;" ::: "memory");
        }
        sidx = (sidx == NSTAGE - 1) ? 0 : sidx + 1;
    }

    // --- epilogue: out[tok] += gate * (acc + be[e]) ---
    const float* beg = be + (size_t)e * HDIM + n0;
    const int cl = (lane & 3) * 2;
    const int rl = lane >> 2;
#pragma unroll
    for (int mi = 0; mi < 4; mi++) {
        const int r0 = wm * 64 + mi * 16 + rl;
        const int r1 = r0 + 8;
        const bool v0 = (m0 + r0) < cnt;
        const bool v1 = (m0 + r1) < cnt;
        const int   t0 = sTok[r0], t1 = sTok[r1];
        const float g0 = sGate[r0], g1 = sGate[r1];
        float* o0 = out + (size_t)t0 * HDIM + n0;
        float* o1 = out + (size_t)t1 * HDIM + n0;
#pragma unroll
        for (int nj = 0; nj < 8; nj++) {
            const int col = wn * 64 + nj * 8 + cl;
            const float b0 = beg[col], b1 = beg[col + 1];
            if (v0) {
                atomicAdd(&o0[col],     g0 * (acc[mi][nj][0] + b0));
                atomicAdd(&o0[col + 1], g0 * (acc[mi][nj][1] + b1));
            }
            if (v1) {
                atomicAdd(&o1[col],     g1 * (acc[mi][nj][2] + b0));
                atomicAdd(&o1[col + 1], g1 * (acc[mi][nj][3] + b1));
            }
        }
    }
}

// ---------------------------------------------------------------------------
extern "C" void kernel_launch(void* const* d_in, const int* in_sizes, int n_in,
                              void* d_out, int out_size) {
    const float* x  = (const float*)d_in[0];
    const float* Wg = (const float*)d_in[1];
    const float* bg = (const float*)d_in[2];
    const float* We = (const float*)d_in[3];
    const float* be = (const float*)d_in[4];
    float* out = (float*)d_out;

    cudaFuncSetAttribute(moe_gemm_mma, cudaFuncAttributeMaxDynamicSharedMemorySize, SMEM_TOTAL);

    init_kernel<<<1024, 256>>>(out);
    convert_x<<<2048, 256>>>(x);
    dim3 tg(HDIM / 32, HDIM / 32, NEXP);
    transpose_we<<<tg, 256>>>(We);
    router_kernel<<<T_TOK / 8, 256>>>(x, Wg, bg);

    dim3 grid(HDIM / BN, T_TOK / BM, NEXP);
    moe_gemm_mma<<<grid, 256, SMEM_TOTAL>>>(be, out);
}